// round 12
// baseline (speedup 1.0000x reference)
#include <cuda_runtime.h>
#include <cuda_fp16.h>

// Problem constants
#define NXv 128
#define NYv 128
#define NZv 8
#define NVOX (NXv * NYv * NZv)   // 131072
#define NVIEW 6
#define NCH 64
#define HFv 116
#define WFv 200
#define FEAT_HW (HFv * WFv)      // 23200
#define IMG_W 1600.0f
#define IMG_H 928.0f

#define PTS_PER_BLK 32           // 256 threads / 8 lanes-per-point

// Channel-last fp16 scratch: [V, HF, WF, C]  (17.8 MB). One tap = 128B line.
__device__ __align__(256) static __half g_feat_h[NVIEW * FEAT_HW * NCH];

// ---------------------------------------------------------------------------
// Kernel 1: transpose+convert [V,C,H,W] fp32 -> [V,H,W,C] fp16.
// ---------------------------------------------------------------------------
__global__ __launch_bounds__(256)
void convert_kernel(const float* __restrict__ xfov)
{
    __shared__ float tile[NCH][33];

    const int w0 = blockIdx.x * 32;
    const int vh = blockIdx.y;            // 0..695
    const int v  = vh / HFv;
    const int h  = vh - v * HFv;

    const int tx = threadIdx.x & 31;
    const int ty = threadIdx.x >> 5;      // 0..7

    const int w = w0 + tx;
    if (w < WFv) {
#pragma unroll
        for (int i = 0; i < 8; i++) {
            const int c = ty + i * 8;
            tile[c][tx] = xfov[((size_t)(v * NCH + c) * HFv + h) * WFv + w];
        }
    }
    __syncthreads();

    __half2* dst = (__half2*)g_feat_h;
#pragma unroll
    for (int j = 0; j < 4; j++) {
        const int ww = w0 + ty + 8 * j;
        if (ww < WFv) {
            const float a = tile[2 * tx + 0][ty + 8 * j];
            const float b = tile[2 * tx + 1][ty + 8 * j];
            dst[(size_t)(v * FEAT_HW + h * WFv + ww) * (NCH / 2) + tx] =
                __floats2half2_rn(a, b);
        }
    }
}

// ---------------------------------------------------------------------------
// Kernel 2: gather. 8 lanes per point (8 channels each).
// Lane r (<6) computes view r's descriptor once. All shuffles batched
// upfront; per-view skip is a warp-UNIFORM branch from one ballot mask.
// One LDG.128 = 4 points x one full 128B tap line.
// ---------------------------------------------------------------------------
__global__ __launch_bounds__(256)
void gather_kernel(const float* __restrict__ points,
                   const float* __restrict__ proj,
                   float* __restrict__ out)
{
    __shared__ float sM[NVIEW * 16];
    __shared__ float s_out[PTS_PER_BLK * 65];   // stride 65: conflict-free

    if (threadIdx.x < NVIEW * 16) sM[threadIdx.x] = proj[threadIdx.x];
    __syncthreads();

    const int lane  = threadIdx.x & 31;
    const int r     = lane & 7;                // lane-in-octet
    const int obase = lane & 24;               // octet base lane
    const int coff  = r * 8;                   // channel offset (halves)
    const int pl    = threadIdx.x >> 3;        // local point 0..31
    const int p     = blockIdx.x * PTS_PER_BLK + pl;

    const int z = p & (NZv - 1);
    const int y = (p >> 3) & (NYv - 1);
    const int x = p >> 10;
    const int n = (z * NYv + y) * NXv + x;

    const float pxw = __ldg(points + n * 3 + 0);
    const float pyw = __ldg(points + n * 3 + 1);
    const float pzw = __ldg(points + n * 3 + 2);

    // --- Projection: this lane computes ONE view (lanes 6,7 are inert) ---
    unsigned my_off, my_w0, my_w1;
    bool valid;
    {
        const int vm = (r < 6) ? r : 0;
        const float* M = &sM[vm * 16];
        const float cx = fmaf(M[0], pxw, fmaf(M[1], pyw, fmaf(M[2],  pzw, M[3])));
        const float cy = fmaf(M[4], pxw, fmaf(M[5], pyw, fmaf(M[6],  pzw, M[7])));
        const float d  = fmaf(M[8], pxw, fmaf(M[9], pyw, fmaf(M[10], pzw, M[11])));

        const float ds = (fabsf(d) > 1e-6f) ? d : 1e-6f;
        const float rr = __fdividef(1.0f, ds);
        const float u  = cx * rr;
        const float vv = cy * rr;

        valid = (d > 0.0f) & (u > 0.0f) & (u < IMG_W)
                           & (vv > 0.0f) & (vv < IMG_H) & (r < 6);

        // Exact power-of-2 scale: WF/IMG_W = HF/IMG_H = 0.125
        const float fx = fmaf(u,  0.125f, -0.5f);
        const float fy = fmaf(vv, 0.125f, -0.5f);
        const float x0f = floorf(fx);
        const float y0f = floorf(fy);
        const int x0 = (int)x0f;
        const int y0 = (int)y0f;
        const float wx1 = fx - x0f;
        const float wy1 = fy - y0f;

        // Base clamped so all 4 taps are in-bounds; edge handling folded
        // into weights (identical to zero-padded bilinear).
        const int bx = min(max(x0, 0), WFv - 2);
        const int by = min(max(y0, 0), HFv - 2);
        float wl = (x0 < 0) ? wx1 : ((x0 >= WFv - 1) ? 0.0f : 1.0f - wx1);
        float wr = (x0 < 0) ? 0.0f : ((x0 >= WFv - 1) ? 1.0f - wx1 : wx1);
        float wt = (y0 < 0) ? wy1 : ((y0 >= HFv - 1) ? 0.0f : 1.0f - wy1);
        float wb = (y0 < 0) ? 0.0f : ((y0 >= HFv - 1) ? 1.0f - wy1 : wy1);

        // FSEL so NaN garbage from invalid projections is squashed.
        wl = valid ? wl : 0.0f;
        wr = valid ? wr : 0.0f;
        wt = valid ? wt : 0.0f;
        wb = valid ? wb : 0.0f;

        const __half2 h0 = __floats2half2_rn(wl * wt, wr * wt); // (w00, w10)
        const __half2 h1 = __floats2half2_rn(wl * wb, wr * wb); // (w01, w11)

        my_off = valid ? (unsigned)((vm * FEAT_HW + by * WFv + bx) * NCH) : 0u;
        my_w0  = *(const unsigned*)&h0;
        my_w1  = *(const unsigned*)&h1;
    }

    // One ballot: bit (obase+v) = point 'obase' valid in view v
    const unsigned mask = __ballot_sync(0xFFFFFFFFu, valid);
    const int cnt = __popc(mask & (0x3Fu << obase));

    // Batch ALL broadcasts upfront (18 independent SHFLs)
    unsigned offv[NVIEW], w0v[NVIEW], w1v[NVIEW];
#pragma unroll
    for (int v = 0; v < NVIEW; v++) {
        offv[v] = __shfl_sync(0xFFFFFFFFu, my_off, obase + v);
        w0v[v]  = __shfl_sync(0xFFFFFFFFu, my_w0,  obase + v);
        w1v[v]  = __shfl_sync(0xFFFFFFFFu, my_w1,  obase + v);
    }

    __half2 acc2[4];
#pragma unroll
    for (int k = 0; k < 4; k++) acc2[k] = __float2half2_rn(0.0f);

#pragma unroll
    for (int v = 0; v < NVIEW; v++) {
        // Warp-uniform skip: any octet valid for this view?
        if (mask & (0x01010101u << v)) {
            const __half* bp = g_feat_h + offv[v] + coff;

            const uint4 t00 = __ldg((const uint4*)(bp));
            const uint4 t10 = __ldg((const uint4*)(bp + NCH));
            const uint4 t01 = __ldg((const uint4*)(bp + WFv * NCH));
            const uint4 t11 = __ldg((const uint4*)(bp + (WFv + 1) * NCH));

            const __half2 wp0 = *(const __half2*)&w0v[v];  // (w00, w10)
            const __half2 wp1 = *(const __half2*)&w1v[v];  // (w01, w11)
            const __half2 hw00 = __low2half2(wp0);
            const __half2 hw10 = __high2half2(wp0);
            const __half2 hw01 = __low2half2(wp1);
            const __half2 hw11 = __high2half2(wp1);

            const __half2* f00 = (const __half2*)&t00;
            const __half2* f10 = (const __half2*)&t10;
            const __half2* f01 = (const __half2*)&t01;
            const __half2* f11 = (const __half2*)&t11;
#pragma unroll
            for (int k = 0; k < 4; k++) {
                __half2 s = __hmul2(f00[k], hw00);
                s = __hfma2(f10[k], hw10, s);
                s = __hfma2(f01[k], hw01, s);
                s = __hfma2(f11[k], hw11, s);
                acc2[k] = __hadd2(acc2[k], s);
            }
        }
    }

    // Stage normalized result in SMEM
    const float inv = (cnt > 0) ? (1.0f / (float)cnt) : 0.0f;
#pragma unroll
    for (int k = 0; k < 4; k++) {
        const float2 sf = __half22float2(acc2[k]);
        s_out[pl * 65 + coff + 2 * k + 0] = sf.x * inv;
        s_out[pl * 65 + coff + 2 * k + 1] = sf.y * inv;
    }
    __syncthreads();

    // Coalesced write-out: 2048 floats; 32 consecutive p per channel = 128B
    const int p0 = blockIdx.x * PTS_PER_BLK;
#pragma unroll
    for (int jj = 0; jj < 8; jj++) {
        const int idx = threadIdx.x + jj * 256;   // 0..2047
        const int c   = idx >> 5;                 // 0..63
        const int ppl = idx & 31;                 // 0..31
        out[(size_t)c * NVOX + p0 + ppl] = s_out[ppl * 65 + c];
    }
}

extern "C" void kernel_launch(void* const* d_in, const int* in_sizes, int n_in,
                              void* d_out, int out_size)
{
    const float* x_fov  = (const float*)d_in[0];  // [1,6,64,116,200]
    const float* points = (const float*)d_in[1];  // [131072,3]
    const float* proj   = (const float*)d_in[2];  // [6,4,4]
    float* out = (float*)d_out;                   // [1,64,128,128,8]

    {
        dim3 blk(256);
        dim3 grd((WFv + 31) / 32, NVIEW * HFv);   // (7, 696)
        convert_kernel<<<grd, blk>>>(x_fov);
    }
    {
        const int blocks = NVOX / PTS_PER_BLK;    // 4096
        gather_kernel<<<blocks, 256>>>(points, proj, out);
    }
}

// round 13
// speedup vs baseline: 1.0371x; 1.0371x over previous
#include <cuda_runtime.h>
#include <cuda_fp16.h>

// Problem constants
#define NXv 128
#define NYv 128
#define NZv 8
#define NVOX (NXv * NYv * NZv)   // 131072
#define NVIEW 6
#define NCH 64
#define HFv 116
#define WFv 200
#define FEAT_HW (HFv * WFv)      // 23200
#define IMG_W 1600.0f
#define IMG_H 928.0f

#define PTS_PER_BLK 32           // 256 threads / 8 lanes-per-point
#define INV_OFF 0xFFFFFFFFu

// Channel-last fp16 scratch: [V, HF, WF, C]  (17.8 MB). One tap = 128B line.
__device__ __align__(256) static __half g_feat_h[NVIEW * FEAT_HW * NCH];
// Per-(point,view) descriptor: .x = base offset (halves) or INV, .y=(w00,w10),
// .z=(w01,w11) packed fp16, .w unused.  12.6 MB.
__device__ __align__(256) static uint4 g_desc[NVOX * NVIEW];

// ---------------------------------------------------------------------------
// Kernel 1: transpose+convert [V,C,H,W] fp32 -> [V,H,W,C] fp16.
// ---------------------------------------------------------------------------
__global__ __launch_bounds__(256)
void convert_kernel(const float* __restrict__ xfov)
{
    __shared__ float tile[NCH][33];

    const int w0 = blockIdx.x * 32;
    const int vh = blockIdx.y;            // 0..695
    const int v  = vh / HFv;
    const int h  = vh - v * HFv;

    const int tx = threadIdx.x & 31;
    const int ty = threadIdx.x >> 5;      // 0..7

    const int w = w0 + tx;
    if (w < WFv) {
#pragma unroll
        for (int i = 0; i < 8; i++) {
            const int c = ty + i * 8;
            tile[c][tx] = xfov[((size_t)(v * NCH + c) * HFv + h) * WFv + w];
        }
    }
    __syncthreads();

    __half2* dst = (__half2*)g_feat_h;
#pragma unroll
    for (int j = 0; j < 4; j++) {
        const int ww = w0 + ty + 8 * j;
        if (ww < WFv) {
            const float a = tile[2 * tx + 0][ty + 8 * j];
            const float b = tile[2 * tx + 1][ty + 8 * j];
            dst[(size_t)(v * FEAT_HW + h * WFv + ww) * (NCH / 2) + tx] =
                __floats2half2_rn(a, b);
        }
    }
}

// ---------------------------------------------------------------------------
// Kernel 2: projection. One thread per (point, view); writes one 16B
// descriptor, coalesced. Projection math happens exactly once per task.
// ---------------------------------------------------------------------------
__global__ __launch_bounds__(256)
void project_kernel(const float* __restrict__ points,
                    const float* __restrict__ proj)
{
    __shared__ float sM[NVIEW * 16];
    if (threadIdx.x < NVIEW * 16) sM[threadIdx.x] = proj[threadIdx.x];
    __syncthreads();

    const int t = blockIdx.x * blockDim.x + threadIdx.x;  // 0..786431
    const int p = t / NVIEW;
    const int v = t - p * NVIEW;

    // Output-linear p -> (x,y,z); point index n = z*NY*NX + y*NX + x
    const int z = p & (NZv - 1);
    const int y = (p >> 3) & (NYv - 1);
    const int x = p >> 10;
    const int n = (z * NYv + y) * NXv + x;

    const float pxw = __ldg(points + n * 3 + 0);
    const float pyw = __ldg(points + n * 3 + 1);
    const float pzw = __ldg(points + n * 3 + 2);

    const float* M = &sM[v * 16];
    const float cx = fmaf(M[0], pxw, fmaf(M[1], pyw, fmaf(M[2],  pzw, M[3])));
    const float cy = fmaf(M[4], pxw, fmaf(M[5], pyw, fmaf(M[6],  pzw, M[7])));
    const float d  = fmaf(M[8], pxw, fmaf(M[9], pyw, fmaf(M[10], pzw, M[11])));

    const float ds = (fabsf(d) > 1e-6f) ? d : 1e-6f;
    const float r  = __fdividef(1.0f, ds);
    const float u  = cx * r;
    const float vv = cy * r;

    const bool valid = (d > 0.0f) & (u > 0.0f) & (u < IMG_W)
                                  & (vv > 0.0f) & (vv < IMG_H);

    uint4 desc;
    desc.x = INV_OFF; desc.y = 0u; desc.z = 0u; desc.w = 0u;

    if (valid) {
        // Exact power-of-2 scale: WF/IMG_W = HF/IMG_H = 0.125
        const float fx = fmaf(u,  0.125f, -0.5f);   // (-0.5, 199.5)
        const float fy = fmaf(vv, 0.125f, -0.5f);   // (-0.5, 115.5)
        const float x0f = floorf(fx);
        const float y0f = floorf(fy);
        const int x0 = (int)x0f;   // [-1, 199]
        const int y0 = (int)y0f;   // [-1, 115]
        const float wx1 = fx - x0f;
        const float wy1 = fy - y0f;

        // Base clamped so all 4 taps are in-bounds; edge handling folded
        // into weights (identical to zero-padded bilinear).
        const int bx = min(max(x0, 0), WFv - 2);
        const int by = min(max(y0, 0), HFv - 2);
        const float wl = (x0 < 0) ? wx1 : ((x0 >= WFv - 1) ? 0.0f : 1.0f - wx1);
        const float wr = (x0 < 0) ? 0.0f : ((x0 >= WFv - 1) ? 1.0f - wx1 : wx1);
        const float wt = (y0 < 0) ? wy1 : ((y0 >= HFv - 1) ? 0.0f : 1.0f - wy1);
        const float wb = (y0 < 0) ? 0.0f : ((y0 >= HFv - 1) ? 1.0f - wy1 : wy1);

        const __half2 h0 = __floats2half2_rn(wl * wt, wr * wt); // (w00, w10)
        const __half2 h1 = __floats2half2_rn(wl * wb, wr * wb); // (w01, w11)

        desc.x = (unsigned)((v * FEAT_HW + by * WFv + bx) * NCH);  // halves
        desc.y = *(const unsigned*)&h0;
        desc.z = *(const unsigned*)&h1;
    }
    g_desc[t] = desc;
}

// ---------------------------------------------------------------------------
// Kernel 3: gather. 8 lanes per point (8 channels each). Descriptors read
// upfront (octet-broadcast LDG.128), per-lane divergent skip, one LDG.128
// per tap = 4 points x one full 128B line. SMEM-staged coalesced stores.
// ---------------------------------------------------------------------------
__global__ __launch_bounds__(256)
void gather_kernel(float* __restrict__ out)
{
    __shared__ float s_out[PTS_PER_BLK * 65];   // stride 65: conflict-free

    const int q  = threadIdx.x & 7;            // channel-eighth
    const int pl = threadIdx.x >> 3;           // local point 0..31
    const int p  = blockIdx.x * PTS_PER_BLK + pl;
    const int coff = q * 8;                    // channel offset (halves)

    // Load all 6 descriptors upfront (independent, broadcast across octet)
    uint4 d0 = __ldg(&g_desc[p * NVIEW + 0]);
    uint4 d1 = __ldg(&g_desc[p * NVIEW + 1]);
    uint4 d2 = __ldg(&g_desc[p * NVIEW + 2]);
    uint4 d3 = __ldg(&g_desc[p * NVIEW + 3]);
    uint4 d4 = __ldg(&g_desc[p * NVIEW + 4]);
    uint4 d5 = __ldg(&g_desc[p * NVIEW + 5]);

    const int cnt = (d0.x != INV_OFF) + (d1.x != INV_OFF) + (d2.x != INV_OFF)
                  + (d3.x != INV_OFF) + (d4.x != INV_OFF) + (d5.x != INV_OFF);

    __half2 acc2[4];
#pragma unroll
    for (int k = 0; k < 4; k++) acc2[k] = __float2half2_rn(0.0f);

    const uint4* dsc[NVIEW] = { &d0, &d1, &d2, &d3, &d4, &d5 };

#pragma unroll
    for (int v = 0; v < NVIEW; v++) {
        const uint4 dv = *dsc[v];
        if (dv.x != INV_OFF) {
            const __half* bp = g_feat_h + dv.x + coff;

            const uint4 t00 = __ldg((const uint4*)(bp));
            const uint4 t10 = __ldg((const uint4*)(bp + NCH));
            const uint4 t01 = __ldg((const uint4*)(bp + WFv * NCH));
            const uint4 t11 = __ldg((const uint4*)(bp + (WFv + 1) * NCH));

            const __half2 wp0 = *(const __half2*)&dv.y;  // (w00, w10)
            const __half2 wp1 = *(const __half2*)&dv.z;  // (w01, w11)
            const __half2 hw00 = __low2half2(wp0);
            const __half2 hw10 = __high2half2(wp0);
            const __half2 hw01 = __low2half2(wp1);
            const __half2 hw11 = __high2half2(wp1);

            const __half2* f00 = (const __half2*)&t00;
            const __half2* f10 = (const __half2*)&t10;
            const __half2* f01 = (const __half2*)&t01;
            const __half2* f11 = (const __half2*)&t11;
#pragma unroll
            for (int k = 0; k < 4; k++) {
                __half2 s = __hmul2(f00[k], hw00);
                s = __hfma2(f10[k], hw10, s);
                s = __hfma2(f01[k], hw01, s);
                s = __hfma2(f11[k], hw11, s);
                acc2[k] = __hadd2(acc2[k], s);
            }
        }
    }

    // Stage normalized result in SMEM
    const float inv = (cnt > 0) ? (1.0f / (float)cnt) : 0.0f;
#pragma unroll
    for (int k = 0; k < 4; k++) {
        const float2 sf = __half22float2(acc2[k]);
        s_out[pl * 65 + coff + 2 * k + 0] = sf.x * inv;
        s_out[pl * 65 + coff + 2 * k + 1] = sf.y * inv;
    }
    __syncthreads();

    // Coalesced write-out: 2048 floats; 32 consecutive p per channel = 128B
    const int p0 = blockIdx.x * PTS_PER_BLK;
#pragma unroll
    for (int jj = 0; jj < 8; jj++) {
        const int idx = threadIdx.x + jj * 256;   // 0..2047
        const int c   = idx >> 5;                 // 0..63
        const int ppl = idx & 31;                 // 0..31
        out[(size_t)c * NVOX + p0 + ppl] = s_out[ppl * 65 + c];
    }
}

extern "C" void kernel_launch(void* const* d_in, const int* in_sizes, int n_in,
                              void* d_out, int out_size)
{
    const float* x_fov  = (const float*)d_in[0];  // [1,6,64,116,200]
    const float* points = (const float*)d_in[1];  // [131072,3]
    const float* proj   = (const float*)d_in[2];  // [6,4,4]
    float* out = (float*)d_out;                   // [1,64,128,128,8]

    {
        dim3 blk(256);
        dim3 grd((WFv + 31) / 32, NVIEW * HFv);   // (7, 696)
        convert_kernel<<<grd, blk>>>(x_fov);
    }
    {
        const int blocks = (NVOX * NVIEW) / 256;  // 3072
        project_kernel<<<blocks, 256>>>(points, proj);
    }
    {
        const int blocks = NVOX / PTS_PER_BLK;    // 4096
        gather_kernel<<<blocks, 256>>>(out);
    }
}